// round 2
// baseline (speedup 1.0000x reference)
#include <cuda_runtime.h>

// ContrastiveLoss (discriminative loss), shapes fixed by the problem:
//   input_:  (4, 32, 512, 512) float32   (B, C, H, W), channel-major
//   target:  (4, 1, 512, 512)  int32     labels in [0, 100)
//            (reference asks jax for int64, but JAX x64 is disabled -> int32)
//   n_instances = 100 (hardcoded)
// Output: scalar float32 loss.

#define BB 4
#define CC 32
#define HW 262144            // 512*512
#define NI 100
#define PITCH 33             // padded row pitch: 32 channels + count/inv slot
#define DVAR 0.75f
#define REP 4.0f             // 2 * DELTA_DIST

__device__ float g_sum[BB * NI * CC];   // per-batch per-label channel sums
__device__ float g_cnt[BB * NI];        // per-batch per-label counts

// ---------------------------------------------------------------------------
__global__ void k_zero(float* __restrict__ out) {
    int i = blockIdx.x * blockDim.x + threadIdx.x;
    if (i < BB * NI * CC) g_sum[i] = 0.0f;
    if (i < BB * NI)      g_cnt[i] = 0.0f;
    if (i == 0)           out[0]   = 0.0f;
}

// ---------------------------------------------------------------------------
// Pass 1: per-label sums + counts.
// Block = 64 threads (2 warps). Each warp owns a private padded table in smem
// (no atomics). Lane = channel. Pixels are staged through a padded smem tile
// so gmem loads stay coalesced while the per-pixel column read is
// bank-conflict-free. Pixels are consumed in groups of 4 with an all-distinct
// label fast path to expose ILP across the smem RMW chains.
__global__ void __launch_bounds__(64) k_pass1(const float* __restrict__ in,
                                              const int* __restrict__ tgt) {
    __shared__ float wtab[2][NI * PITCH];   // 26,400 B
    __shared__ float tile[2][64 * PITCH];   // 16,896 B
    __shared__ int   lbl[2][64];            //     512 B

    const int b    = blockIdx.y;
    const int warp = threadIdx.x >> 5;
    const int lane = threadIdx.x & 31;
    float* T  = wtab[warp];
    float* TL = tile[warp];
    int*   L  = lbl[warp];

    for (int i = threadIdx.x; i < 2 * NI * PITCH; i += 64)
        (&wtab[0][0])[i] = 0.0f;
    __syncthreads();

    const float* inb = in  + (size_t)b * CC * HW;
    const int*   tb  = tgt + (size_t)b * HW;
    const int base = blockIdx.x * 2048 + warp * 1024;   // 1024 px per warp

    for (int t = 0; t < 16; ++t) {
        const int p0 = base + t * 64;
        // stage labels (2 per lane) and features (tile[p][c], pitch 33)
        L[lane]      = tb[p0 + lane];
        L[lane + 32] = tb[p0 + 32 + lane];
#pragma unroll
        for (int c = 0; c < CC; ++c) {
            const float* row = inb + (size_t)c * HW + p0;
            TL[lane * PITCH + c]        = row[lane];          // coalesced LDG
            TL[(lane + 32) * PITCH + c] = row[lane + 32];
        }
        __syncwarp();

#pragma unroll
        for (int g = 0; g < 16; ++g) {
            const int l0 = L[4*g+0], l1 = L[4*g+1], l2 = L[4*g+2], l3 = L[4*g+3];
            const float v0 = TL[(4*g+0) * PITCH + lane];
            const float v1 = TL[(4*g+1) * PITCH + lane];
            const float v2 = TL[(4*g+2) * PITCH + lane];
            const float v3 = TL[(4*g+3) * PITCH + lane];
            const bool distinct = (l0 != l1) & (l0 != l2) & (l0 != l3) &
                                  (l1 != l2) & (l1 != l3) & (l2 != l3);
            if (distinct) {
                // addresses provably distinct: batch loads, then stores (4-wide ILP)
                float a0 = T[l0 * PITCH + lane];
                float a1 = T[l1 * PITCH + lane];
                float a2 = T[l2 * PITCH + lane];
                float a3 = T[l3 * PITCH + lane];
                T[l0 * PITCH + lane] = a0 + v0;
                T[l1 * PITCH + lane] = a1 + v1;
                T[l2 * PITCH + lane] = a2 + v2;
                T[l3 * PITCH + lane] = a3 + v3;
                if (lane == 0) {
                    float c0 = T[l0 * PITCH + 32];
                    float c1 = T[l1 * PITCH + 32];
                    float c2 = T[l2 * PITCH + 32];
                    float c3 = T[l3 * PITCH + 32];
                    T[l0 * PITCH + 32] = c0 + 1.0f;
                    T[l1 * PITCH + 32] = c1 + 1.0f;
                    T[l2 * PITCH + 32] = c2 + 1.0f;
                    T[l3 * PITCH + 32] = c3 + 1.0f;
                }
            } else {
                // rare (<7%): serialized RMWs, correct for any duplicate pattern
                T[l0 * PITCH + lane] += v0;
                T[l1 * PITCH + lane] += v1;
                T[l2 * PITCH + lane] += v2;
                T[l3 * PITCH + lane] += v3;
                if (lane == 0) {
                    T[l0 * PITCH + 32] += 1.0f;
                    T[l1 * PITCH + 32] += 1.0f;
                    T[l2 * PITCH + 32] += 1.0f;
                    T[l3 * PITCH + 32] += 1.0f;
                }
            }
        }
        __syncwarp();
    }
    __syncthreads();

    // flush block (2 warp tables) to global with atomics
    for (int i = threadIdx.x; i < NI * CC; i += 64) {
        const int l = i >> 5, c = i & 31;
        const float s = wtab[0][l * PITCH + c] + wtab[1][l * PITCH + c];
        atomicAdd(&g_sum[(b * NI + l) * CC + c], s);
    }
    for (int i = threadIdx.x; i < NI; i += 64)
        atomicAdd(&g_cnt[b * NI + i],
                  wtab[0][i * PITCH + 32] + wtab[1][i * PITCH + 32]);
}

// ---------------------------------------------------------------------------
// Pass 2: variance term (blocks 0..255 per batch) + pairwise-distance and
// regularizer terms (block 256 per batch, overlapped on the same launch).
__global__ void __launch_bounds__(256) k_var(const float* __restrict__ in,
                                             const int* __restrict__ tgt,
                                             float* __restrict__ out) {
    __shared__ float sm[NI * PITCH];        // means (32) + inv_count (slot 32)
    __shared__ float red[8];

    const int b = blockIdx.y;
    for (int i = threadIdx.x; i < NI; i += 256) {
        const float inv = 1.0f / g_cnt[b * NI + i];
#pragma unroll
        for (int c = 0; c < CC; ++c)
            sm[i * PITCH + c] = g_sum[(b * NI + i) * CC + c] * inv;
        sm[i * PITCH + 32] = inv;
    }
    __syncthreads();

    float acc = 0.0f;
    if (blockIdx.x < 256) {
        const float* inb = in  + (size_t)b * CC * HW;
        const int*   tb  = tgt + (size_t)b * HW;
        const int p0 = blockIdx.x * 1024 + threadIdx.x;
#pragma unroll
        for (int k = 0; k < 4; ++k) {
            const int p = p0 + k * 256;
            const int l = tb[p];
            const float* m = sm + l * PITCH;
            float d2 = 0.0f;
#pragma unroll
            for (int c = 0; c < CC; ++c) {
                const float v = inb[(size_t)c * HW + p] - m[c];
                d2 = fmaf(v, v, d2);
            }
            const float r = sqrtf(d2);
            const float h = fmaxf(r - DVAR, 0.0f);
            acc = fmaf(h * h, m[32], acc);
        }
        acc *= (1.0f / (NI * BB));                         // ALPHA = 1
    } else {
        // distance + regularizer terms for this batch
        float accd = 0.0f, accr = 0.0f;
        for (int idx = threadIdx.x; idx < NI * NI; idx += 256) {
            const int i = idx / NI, j = idx - i * NI;
            if (i == j) continue;
            float d2 = 0.0f;
#pragma unroll
            for (int c = 0; c < CC; ++c) {
                const float v = sm[i * PITCH + c] - sm[j * PITCH + c];
                d2 = fmaf(v, v, d2);
            }
            const float d = (d2 > 0.0f) ? sqrtf(d2) : 1.0f;
            const float h = fmaxf(REP - d, 0.0f);
            accd = fmaf(h, h, accd);
        }
        for (int i = threadIdx.x; i < NI; i += 256) {
            float n2 = 0.0f;
#pragma unroll
            for (int c = 0; c < CC; ++c) {
                const float v = sm[i * PITCH + c];
                n2 = fmaf(v, v, n2);
            }
            accr += sqrtf(n2);
        }
        acc = accd * (1.0f / (NI * (NI - 1) * BB))          // BETA = 1
            + accr * (0.001f / (NI * BB));                  // GAMMA = 0.001
    }

    // block reduce
#pragma unroll
    for (int o = 16; o > 0; o >>= 1) acc += __shfl_down_sync(0xffffffffu, acc, o);
    if ((threadIdx.x & 31) == 0) red[threadIdx.x >> 5] = acc;
    __syncthreads();
    if (threadIdx.x < 32) {
        float v = (threadIdx.x < 8) ? red[threadIdx.x] : 0.0f;
#pragma unroll
        for (int o = 4; o > 0; o >>= 1) v += __shfl_down_sync(0xffffffffu, v, o);
        if (threadIdx.x == 0) atomicAdd(out, v);
    }
}

// ---------------------------------------------------------------------------
extern "C" void kernel_launch(void* const* d_in, const int* in_sizes, int n_in,
                              void* d_out, int out_size) {
    const float* in  = (const float*)d_in[0];
    const int*   tgt = (const int*)d_in[1];
    float* out = (float*)d_out;

    k_zero<<<50, 256>>>(out);
    dim3 g1(128, BB);
    k_pass1<<<g1, 64>>>(in, tgt);
    dim3 g2(257, BB);
    k_var<<<g2, 256>>>(in, tgt, out);
}